// round 1
// baseline (speedup 1.0000x reference)
#include <cuda_runtime.h>
#include <math.h>

#define S_LEN 4096
#define DIM 1024
#define NH 16
#define HD 64
#define HALF_HD 32

// Intermediate buffers (allocation-free scratch)
__device__ float g_q[S_LEN * DIM];
__device__ float g_k[S_LEN * DIM];
__device__ float g_v[S_LEN * DIM];
__device__ float g_o[S_LEN * DIM];
__device__ float g_cos[S_LEN * HALF_HD];
__device__ float g_sin[S_LEN * HALF_HD];

// ---------------------------------------------------------------------------
// SGEMM: C[M,N] = A[M,K] * B[N,K]^T   (both A and B k-contiguous row-major)
// BM=BN=128, BK=16, 256 threads, 8x8 microtile per thread.
// ---------------------------------------------------------------------------
#define BM 128
#define BN 128
#define BKK 16

__global__ __launch_bounds__(256) void sgemm_abt(
    const float* __restrict__ A, const float* __restrict__ B,
    float* __restrict__ C, int M, int N, int K)
{
    __shared__ float As[BKK][BM];
    __shared__ float Bs[BKK][BN];

    const int tid = threadIdx.x;
    const int tx = tid % 16;          // 0..15  -> 8 cols each
    const int ty = tid / 16;          // 0..15  -> 8 rows each
    const int bm = blockIdx.y * BM;
    const int bn = blockIdx.x * BN;

    float acc[8][8];
    #pragma unroll
    for (int i = 0; i < 8; i++)
        #pragma unroll
        for (int j = 0; j < 8; j++) acc[i][j] = 0.0f;

    for (int k0 = 0; k0 < K; k0 += BKK) {
        // Load A tile (128x16) transposed into As[k][m]
        #pragma unroll
        for (int i = tid; i < BM * BKK / 4; i += 256) {
            int row = i >> 2;          // BKK/4 = 4 float4 per row
            int kc4 = i & 3;
            float4 v = *(const float4*)(A + (size_t)(bm + row) * K + k0 + kc4 * 4);
            As[kc4 * 4 + 0][row] = v.x;
            As[kc4 * 4 + 1][row] = v.y;
            As[kc4 * 4 + 2][row] = v.z;
            As[kc4 * 4 + 3][row] = v.w;
        }
        // Load B tile (128x16) transposed into Bs[k][n]
        #pragma unroll
        for (int i = tid; i < BN * BKK / 4; i += 256) {
            int row = i >> 2;
            int kc4 = i & 3;
            float4 v = *(const float4*)(B + (size_t)(bn + row) * K + k0 + kc4 * 4);
            Bs[kc4 * 4 + 0][row] = v.x;
            Bs[kc4 * 4 + 1][row] = v.y;
            Bs[kc4 * 4 + 2][row] = v.z;
            Bs[kc4 * 4 + 3][row] = v.w;
        }
        __syncthreads();

        #pragma unroll
        for (int kk = 0; kk < BKK; kk++) {
            float4 a0 = *(const float4*)&As[kk][ty * 8];
            float4 a1 = *(const float4*)&As[kk][ty * 8 + 4];
            float4 b0 = *(const float4*)&Bs[kk][tx * 8];
            float4 b1 = *(const float4*)&Bs[kk][tx * 8 + 4];
            float ra[8] = {a0.x, a0.y, a0.z, a0.w, a1.x, a1.y, a1.z, a1.w};
            float rb[8] = {b0.x, b0.y, b0.z, b0.w, b1.x, b1.y, b1.z, b1.w};
            #pragma unroll
            for (int i = 0; i < 8; i++)
                #pragma unroll
                for (int j = 0; j < 8; j++)
                    acc[i][j] += ra[i] * rb[j];
        }
        __syncthreads();
    }

    #pragma unroll
    for (int i = 0; i < 8; i++) {
        float* crow = C + (size_t)(bm + ty * 8 + i) * N + bn + tx * 8;
        *(float4*)(crow)     = make_float4(acc[i][0], acc[i][1], acc[i][2], acc[i][3]);
        *(float4*)(crow + 4) = make_float4(acc[i][4], acc[i][5], acc[i][6], acc[i][7]);
    }
}

// ---------------------------------------------------------------------------
// RoPE tables (double precision internally; closer to exact than fp32 ref)
// ---------------------------------------------------------------------------
__global__ void rope_table_kernel()
{
    int idx = blockIdx.x * blockDim.x + threadIdx.x;
    if (idx >= S_LEN * HALF_HD) return;
    int s = idx / HALF_HD;
    int p = idx % HALF_HD;
    double inv = pow(10000.0, -(double)(2 * p) / 64.0);
    double ang = (double)s * inv;
    g_cos[idx] = (float)cos(ang);
    g_sin[idx] = (float)sin(ang);
}

// Interleaved-pair RoPE, in place. One thread per (s, h, p) pair.
__global__ void rope_apply_kernel(float* __restrict__ t)
{
    int idx = blockIdx.x * blockDim.x + threadIdx.x;
    if (idx >= S_LEN * NH * HALF_HD) return;
    int p = idx % HALF_HD;
    int h = (idx / HALF_HD) % NH;
    int s = idx / (HALF_HD * NH);
    float c  = g_cos[s * HALF_HD + p];
    float sn = g_sin[s * HALF_HD + p];
    float2* base = (float2*)(t + (size_t)s * DIM + h * HD + 2 * p);
    float2 x = *base;
    float2 y;
    y.x = x.x * c - x.y * sn;
    y.y = x.y * c + x.x * sn;
    *base = y;
}

// ---------------------------------------------------------------------------
// Causal flash attention, fp32. Block = 128 threads = 128 query rows for
// one head. Key tiles of 64 staged in shared; two-pass online softmax with
// scores in padded shared (stride 65 -> conflict free). q, acc in registers.
// ---------------------------------------------------------------------------
#define QT 128
#define KT 64
#define SC_PITCH 65
#define FLASH_SMEM ((2 * KT * HD + QT * SC_PITCH) * (int)sizeof(float))

__global__ __launch_bounds__(128) void flash_attn_kernel()
{
    extern __shared__ float sh[];
    float* Ks = sh;                 // KT*HD
    float* Vs = sh + KT * HD;       // KT*HD
    float* Sc = sh + 2 * KT * HD;   // QT*SC_PITCH

    const int h   = blockIdx.y;
    const int qt  = blockIdx.x;
    const int tid = threadIdx.x;
    const int qrow = qt * QT + tid;

    const float* qptr = g_q + (size_t)qrow * DIM + h * HD;
    float4 qv[16];
    #pragma unroll
    for (int i = 0; i < 16; i++) qv[i] = *(const float4*)(qptr + i * 4);

    float4 av[16];
    #pragma unroll
    for (int i = 0; i < 16; i++) av[i] = make_float4(0.f, 0.f, 0.f, 0.f);

    float m = -1e30f, l = 0.0f;
    const float scale = 0.125f;     // 1/sqrt(64)

    const int nkt = 2 * qt + 2;     // causal: only tiles with key <= max query
    for (int kt = 0; kt < nkt; kt++) {
        // Cooperative K/V tile load (64 rows x 64 dims, float4)
        #pragma unroll
        for (int i = tid; i < KT * HD / 4; i += 128) {
            int r  = i >> 4;        // HD/4 = 16
            int c4 = i & 15;
            size_t g = (size_t)(kt * KT + r) * DIM + h * HD + c4 * 4;
            *(float4*)&Ks[r * HD + c4 * 4] = *(const float4*)(g_k + g);
            *(float4*)&Vs[r * HD + c4 * 4] = *(const float4*)(g_v + g);
        }
        __syncthreads();

        // Pass 1: scores + tile max
        float tmax = -1e30f;
        for (int kk = 0; kk < KT; kk++) {
            float s0 = 0.f, s1 = 0.f, s2 = 0.f, s3 = 0.f;
            #pragma unroll
            for (int d4 = 0; d4 < 16; d4++) {
                float4 kvv = *(const float4*)&Ks[kk * HD + d4 * 4];
                s0 += qv[d4].x * kvv.x;
                s1 += qv[d4].y * kvv.y;
                s2 += qv[d4].z * kvv.z;
                s3 += qv[d4].w * kvv.w;
            }
            float s = (s0 + s1) + (s2 + s3);
            int kg = kt * KT + kk;
            s = (kg <= qrow) ? s * scale : -1e30f;
            Sc[tid * SC_PITCH + kk] = s;
            tmax = fmaxf(tmax, s);
        }

        // Online softmax rescale
        float mnew  = fmaxf(m, tmax);
        float alpha = __expf(m - mnew);
        l *= alpha;
        #pragma unroll
        for (int i = 0; i < 16; i++) {
            av[i].x *= alpha; av[i].y *= alpha;
            av[i].z *= alpha; av[i].w *= alpha;
        }
        m = mnew;

        // Pass 2: probs * V
        for (int kk = 0; kk < KT; kk++) {
            float p = __expf(Sc[tid * SC_PITCH + kk] - m);
            l += p;
            #pragma unroll
            for (int d4 = 0; d4 < 16; d4++) {
                float4 vv = *(const float4*)&Vs[kk * HD + d4 * 4];
                av[d4].x += p * vv.x;
                av[d4].y += p * vv.y;
                av[d4].z += p * vv.z;
                av[d4].w += p * vv.w;
            }
        }
        __syncthreads();
    }

    float inv = 1.0f / l;
    float* optr = g_o + (size_t)qrow * DIM + h * HD;
    #pragma unroll
    for (int i = 0; i < 16; i++) {
        float4 o = make_float4(av[i].x * inv, av[i].y * inv,
                               av[i].z * inv, av[i].w * inv);
        *(float4*)(optr + i * 4) = o;
    }
}

// ---------------------------------------------------------------------------
// Launch
// ---------------------------------------------------------------------------
extern "C" void kernel_launch(void* const* d_in, const int* in_sizes, int n_in,
                              void* d_out, int out_size)
{
    const float* x  = (const float*)d_in[0];
    const float* Wq = (const float*)d_in[1];
    const float* Wk = (const float*)d_in[2];
    const float* Wv = (const float*)d_in[3];
    const float* Wo = (const float*)d_in[4];
    float* out = (float*)d_out;

    float *gq, *gk, *gv, *go;
    cudaGetSymbolAddress((void**)&gq, g_q);
    cudaGetSymbolAddress((void**)&gk, g_k);
    cudaGetSymbolAddress((void**)&gv, g_v);
    cudaGetSymbolAddress((void**)&go, g_o);

    cudaFuncSetAttribute(flash_attn_kernel,
                         cudaFuncAttributeMaxDynamicSharedMemorySize, FLASH_SMEM);

    dim3 gg(DIM / BN, S_LEN / BM);   // (8, 32)

    sgemm_abt<<<gg, 256>>>(x, Wq, gq, S_LEN, DIM, DIM);
    sgemm_abt<<<gg, 256>>>(x, Wk, gk, S_LEN, DIM, DIM);
    sgemm_abt<<<gg, 256>>>(x, Wv, gv, S_LEN, DIM, DIM);

    rope_table_kernel<<<(S_LEN * HALF_HD + 255) / 256, 256>>>();
    rope_apply_kernel<<<(S_LEN * NH * HALF_HD + 255) / 256, 256>>>(gq);
    rope_apply_kernel<<<(S_LEN * NH * HALF_HD + 255) / 256, 256>>>(gk);

    flash_attn_kernel<<<dim3(S_LEN / QT, NH), 128, FLASH_SMEM>>>();

    sgemm_abt<<<gg, 256>>>(go, Wo, out, S_LEN, DIM, DIM);
}

// round 3
// speedup vs baseline: 1.2855x; 1.2855x over previous
#include <cuda_runtime.h>
#include <cstdint>
#include <math.h>

#define S_LEN 4096
#define DIM 1024
#define NH 16
#define HD 64
#define HALF_HD 32

// ---------------------------------------------------------------------------
// Scratch (allocation-free)
// ---------------------------------------------------------------------------
__device__ float g_q[S_LEN * DIM];
__device__ float g_k[S_LEN * DIM];
__device__ float g_v[S_LEN * DIM];
__device__ float g_o[S_LEN * DIM];
__device__ float g_xr[S_LEN * DIM];        // x rounded to tf32
__device__ float g_wr[4 * DIM * DIM];      // Wq,Wk,Wv,Wo rounded to tf32
__device__ float g_cos[S_LEN * HALF_HD];
__device__ float g_sin[S_LEN * HALF_HD];

// ---------------------------------------------------------------------------
// Helpers
// ---------------------------------------------------------------------------
__device__ __forceinline__ uint32_t smem_u32(const void* p) {
    uint32_t a;
    asm("{ .reg .u64 t; cvta.to.shared.u64 t, %1; cvt.u32.u64 %0, t; }"
        : "=r"(a) : "l"(p));
    return a;
}

#define CP16(dst, src) \
    asm volatile("cp.async.cg.shared.global [%0], [%1], 16;" :: "r"(dst), "l"(src))
#define CP_COMMIT() asm volatile("cp.async.commit_group;" ::: "memory")
#define CP_WAIT(n)  asm volatile("cp.async.wait_group %0;" :: "n"(n) : "memory")

__device__ __forceinline__ void mma_tf32(float* c, const uint32_t* a, const uint32_t* b)
{
    asm volatile(
        "mma.sync.aligned.m16n8k8.row.col.f32.tf32.tf32.f32 "
        "{%0,%1,%2,%3}, {%4,%5,%6,%7}, {%8,%9}, {%0,%1,%2,%3};"
        : "+f"(c[0]), "+f"(c[1]), "+f"(c[2]), "+f"(c[3])
        : "r"(a[0]), "r"(a[1]), "r"(a[2]), "r"(a[3]), "r"(b[0]), "r"(b[1]));
}

// ---------------------------------------------------------------------------
// tf32 tensor-core GEMM: C[M,N] = A[M,K] * B[N,K]^T
// 128x128 tile, 256 threads, 8 warps (2 m x 4 n), warp tile 64x32.
// BK=32, 2-stage cp.async pipeline. SMEM row pitch 36 floats (conflict-free).
// ---------------------------------------------------------------------------
#define APITCH 36
#define STAGE_BYTES (128 * APITCH * 4)           // 18432
#define GEMM_SMEM (4 * STAGE_BYTES)              // 73728 (A0,A1,B0,B1)

__global__ __launch_bounds__(256) void gemm_mma(
    const float* __restrict__ A, const float* __restrict__ B,
    float* __restrict__ C, int M, int N, int K)
{
    extern __shared__ char sh[];
    const uint32_t sbase = smem_u32(sh);
    const int tid  = threadIdx.x;
    const int lane = tid & 31;
    const int wid  = tid >> 5;
    const int warp_m = wid >> 2;   // 0..1 (64 rows each)
    const int warp_n = wid & 3;    // 0..3 (32 cols each)
    const int bm = blockIdx.y * 128;
    const int bn = blockIdx.x * 128;

    float c[4][4][4];
    #pragma unroll
    for (int i = 0; i < 4; i++)
        #pragma unroll
        for (int j = 0; j < 4; j++)
            #pragma unroll
            for (int k = 0; k < 4; k++) c[i][j][k] = 0.0f;

    const int NK = K >> 5;

    // stage s: A at s*STAGE_BYTES, B at 2*STAGE_BYTES + s*STAGE_BYTES
    #define LOAD_TILE(s, kt) do {                                              \
        const float* Ag = A + (size_t)bm * K + (kt) * 32;                      \
        const float* Bg = B + (size_t)bn * K + (kt) * 32;                      \
        uint32_t adst = sbase + (s) * STAGE_BYTES;                             \
        uint32_t bdst = sbase + 2 * STAGE_BYTES + (s) * STAGE_BYTES;           \
        _Pragma("unroll")                                                      \
        for (int i = 0; i < 4; i++) {                                          \
            int idx = tid + i * 256;                                           \
            int row = idx >> 3, c4 = idx & 7;                                  \
            CP16(adst + row * 144 + c4 * 16, Ag + (size_t)row * K + c4 * 4);   \
            CP16(bdst + row * 144 + c4 * 16, Bg + (size_t)row * K + c4 * 4);   \
        }                                                                      \
    } while (0)

    LOAD_TILE(0, 0);
    CP_COMMIT();

    for (int kt = 0; kt < NK; kt++) {
        if (kt + 1 < NK) {
            LOAD_TILE((kt + 1) & 1, kt + 1);
            CP_COMMIT();
            CP_WAIT(1);
        } else {
            CP_WAIT(0);
        }
        __syncthreads();

        const uint32_t* as = (const uint32_t*)(sh + (kt & 1) * STAGE_BYTES);
        const uint32_t* bs = (const uint32_t*)(sh + 2 * STAGE_BYTES + (kt & 1) * STAGE_BYTES);

        #pragma unroll
        for (int ks = 0; ks < 4; ks++) {
            const int kc = ks * 8 + (lane & 3);
            uint32_t af[4][4], bf[4][2];
            #pragma unroll
            for (int mi = 0; mi < 4; mi++) {
                int r = warp_m * 64 + mi * 16 + (lane >> 2);
                af[mi][0] = as[r * APITCH + kc];
                af[mi][1] = as[(r + 8) * APITCH + kc];
                af[mi][2] = as[r * APITCH + kc + 4];
                af[mi][3] = as[(r + 8) * APITCH + kc + 4];
            }
            #pragma unroll
            for (int ni = 0; ni < 4; ni++) {
                int n = warp_n * 32 + ni * 8 + (lane >> 2);
                bf[ni][0] = bs[n * APITCH + kc];
                bf[ni][1] = bs[n * APITCH + kc + 4];
            }
            #pragma unroll
            for (int mi = 0; mi < 4; mi++)
                #pragma unroll
                for (int ni = 0; ni < 4; ni++)
                    mma_tf32(c[mi][ni], af[mi], bf[ni]);
        }
        __syncthreads();
    }

    // Epilogue: c0,c1 at (r, 2c),(r, 2c+1); c2,c3 at (r+8, ...)
    #pragma unroll
    for (int mi = 0; mi < 4; mi++) {
        int r0 = bm + warp_m * 64 + mi * 16 + (lane >> 2);
        #pragma unroll
        for (int ni = 0; ni < 4; ni++) {
            int col = bn + warp_n * 32 + ni * 8 + 2 * (lane & 3);
            *(float2*)(C + (size_t)r0 * N + col) =
                make_float2(c[mi][ni][0], c[mi][ni][1]);
            *(float2*)(C + (size_t)(r0 + 8) * N + col) =
                make_float2(c[mi][ni][2], c[mi][ni][3]);
        }
    }
}

// ---------------------------------------------------------------------------
// Round fp32 -> tf32 (RN) elementwise
// ---------------------------------------------------------------------------
__global__ void round_tf32_kernel(const float4* __restrict__ in,
                                  float4* __restrict__ out, int n4)
{
    int i = blockIdx.x * blockDim.x + threadIdx.x;
    if (i >= n4) return;
    float4 v = in[i];
    uint32_t a, b, c, d;
    asm("cvt.rna.tf32.f32 %0, %1;" : "=r"(a) : "f"(v.x));
    asm("cvt.rna.tf32.f32 %0, %1;" : "=r"(b) : "f"(v.y));
    asm("cvt.rna.tf32.f32 %0, %1;" : "=r"(c) : "f"(v.z));
    asm("cvt.rna.tf32.f32 %0, %1;" : "=r"(d) : "f"(v.w));
    out[i] = make_float4(__uint_as_float(a), __uint_as_float(b),
                         __uint_as_float(c), __uint_as_float(d));
}

// ---------------------------------------------------------------------------
// RoPE
// ---------------------------------------------------------------------------
__global__ void rope_table_kernel()
{
    int idx = blockIdx.x * blockDim.x + threadIdx.x;
    if (idx >= S_LEN * HALF_HD) return;
    int s = idx / HALF_HD;
    int p = idx % HALF_HD;
    double inv = pow(10000.0, -(double)(2 * p) / 64.0);
    double ang = (double)s * inv;
    g_cos[idx] = (float)cos(ang);
    g_sin[idx] = (float)sin(ang);
}

__global__ void rope_apply_kernel(float* __restrict__ t)
{
    int idx = blockIdx.x * blockDim.x + threadIdx.x;
    if (idx >= S_LEN * NH * HALF_HD) return;
    int p = idx % HALF_HD;
    int h = (idx / HALF_HD) % NH;
    int s = idx / (HALF_HD * NH);
    float c  = g_cos[s * HALF_HD + p];
    float sn = g_sin[s * HALF_HD + p];
    float2* base = (float2*)(t + (size_t)s * DIM + h * HD + 2 * p);
    float2 x = *base;
    float2 y;
    y.x = x.x * c - x.y * sn;
    y.y = x.y * c + x.x * sn;
    *base = y;
}

// ---------------------------------------------------------------------------
// Causal flash attention, fp32 (R1 version, output rounded to tf32)
// ---------------------------------------------------------------------------
#define QT 128
#define KT 64
#define SC_PITCH 65
#define FLASH_SMEM ((2 * KT * HD + QT * SC_PITCH) * (int)sizeof(float))

__global__ __launch_bounds__(128) void flash_attn_kernel()
{
    extern __shared__ float shf[];
    float* Ks = shf;
    float* Vs = shf + KT * HD;
    float* Sc = shf + 2 * KT * HD;

    const int h   = blockIdx.y;
    const int qt  = blockIdx.x;
    const int tid = threadIdx.x;
    const int qrow = qt * QT + tid;

    const float* qptr = g_q + (size_t)qrow * DIM + h * HD;
    float4 qv[16];
    #pragma unroll
    for (int i = 0; i < 16; i++) qv[i] = *(const float4*)(qptr + i * 4);

    float4 av[16];
    #pragma unroll
    for (int i = 0; i < 16; i++) av[i] = make_float4(0.f, 0.f, 0.f, 0.f);

    float m = -1e30f, l = 0.0f;
    const float scale = 0.125f;

    const int nkt = 2 * qt + 2;
    for (int kt = 0; kt < nkt; kt++) {
        #pragma unroll
        for (int i = tid; i < KT * HD / 4; i += 128) {
            int r  = i >> 4;
            int c4 = i & 15;
            size_t g = (size_t)(kt * KT + r) * DIM + h * HD + c4 * 4;
            *(float4*)&Ks[r * HD + c4 * 4] = *(const float4*)(g_k + g);
            *(float4*)&Vs[r * HD + c4 * 4] = *(const float4*)(g_v + g);
        }
        __syncthreads();

        float tmax = -1e30f;
        for (int kk = 0; kk < KT; kk++) {
            float s0 = 0.f, s1 = 0.f, s2 = 0.f, s3 = 0.f;
            #pragma unroll
            for (int d4 = 0; d4 < 16; d4++) {
                float4 kvv = *(const float4*)&Ks[kk * HD + d4 * 4];
                s0 += qv[d4].x * kvv.x;
                s1 += qv[d4].y * kvv.y;
                s2 += qv[d4].z * kvv.z;
                s3 += qv[d4].w * kvv.w;
            }
            float s = (s0 + s1) + (s2 + s3);
            int kg = kt * KT + kk;
            s = (kg <= qrow) ? s * scale : -1e30f;
            Sc[tid * SC_PITCH + kk] = s;
            tmax = fmaxf(tmax, s);
        }

        float mnew  = fmaxf(m, tmax);
        float alpha = __expf(m - mnew);
        l *= alpha;
        #pragma unroll
        for (int i = 0; i < 16; i++) {
            av[i].x *= alpha; av[i].y *= alpha;
            av[i].z *= alpha; av[i].w *= alpha;
        }
        m = mnew;

        for (int kk = 0; kk < KT; kk++) {
            float p = __expf(Sc[tid * SC_PITCH + kk] - m);
            l += p;
            #pragma unroll
            for (int d4 = 0; d4 < 16; d4++) {
                float4 vv = *(const float4*)&Vs[kk * HD + d4 * 4];
                av[d4].x += p * vv.x;
                av[d4].y += p * vv.y;
                av[d4].z += p * vv.z;
                av[d4].w += p * vv.w;
            }
        }
        __syncthreads();
    }

    float inv = 1.0f / l;
    float* optr = g_o + (size_t)qrow * DIM + h * HD;
    #pragma unroll
    for (int i = 0; i < 16; i++) {
        float o0 = av[i].x * inv, o1 = av[i].y * inv;
        float o2 = av[i].z * inv, o3 = av[i].w * inv;
        uint32_t u0, u1, u2, u3;     // round to tf32 for the final GEMM
        asm("cvt.rna.tf32.f32 %0, %1;" : "=r"(u0) : "f"(o0));
        asm("cvt.rna.tf32.f32 %0, %1;" : "=r"(u1) : "f"(o1));
        asm("cvt.rna.tf32.f32 %0, %1;" : "=r"(u2) : "f"(o2));
        asm("cvt.rna.tf32.f32 %0, %1;" : "=r"(u3) : "f"(o3));
        *(float4*)(optr + i * 4) = make_float4(
            __uint_as_float(u0), __uint_as_float(u1),
            __uint_as_float(u2), __uint_as_float(u3));
    }
}

// ---------------------------------------------------------------------------
// Launch
// ---------------------------------------------------------------------------
extern "C" void kernel_launch(void* const* d_in, const int* in_sizes, int n_in,
                              void* d_out, int out_size)
{
    const float* x  = (const float*)d_in[0];
    const float* Wq = (const float*)d_in[1];
    const float* Wk = (const float*)d_in[2];
    const float* Wv = (const float*)d_in[3];
    const float* Wo = (const float*)d_in[4];
    float* out = (float*)d_out;

    float *gq, *gk, *gv, *go, *gxr, *gwr;
    cudaGetSymbolAddress((void**)&gq, g_q);
    cudaGetSymbolAddress((void**)&gk, g_k);
    cudaGetSymbolAddress((void**)&gv, g_v);
    cudaGetSymbolAddress((void**)&go, g_o);
    cudaGetSymbolAddress((void**)&gxr, g_xr);
    cudaGetSymbolAddress((void**)&gwr, g_wr);

    cudaFuncSetAttribute(flash_attn_kernel,
                         cudaFuncAttributeMaxDynamicSharedMemorySize, FLASH_SMEM);
    cudaFuncSetAttribute(gemm_mma,
                         cudaFuncAttributeMaxDynamicSharedMemorySize, GEMM_SMEM);

    const int XW4 = S_LEN * DIM / 4;
    const int W4  = DIM * DIM / 4;
    round_tf32_kernel<<<(XW4 + 255) / 256, 256>>>((const float4*)x,  (float4*)gxr, XW4);
    round_tf32_kernel<<<(W4 + 255) / 256, 256>>>((const float4*)Wq, (float4*)(gwr + 0 * DIM * DIM), W4);
    round_tf32_kernel<<<(W4 + 255) / 256, 256>>>((const float4*)Wk, (float4*)(gwr + 1 * DIM * DIM), W4);
    round_tf32_kernel<<<(W4 + 255) / 256, 256>>>((const float4*)Wv, (float4*)(gwr + 2 * DIM * DIM), W4);
    round_tf32_kernel<<<(W4 + 255) / 256, 256>>>((const float4*)Wo, (float4*)(gwr + 3 * DIM * DIM), W4);

    dim3 gg(DIM / 128, S_LEN / 128);   // (8, 32)
    gemm_mma<<<gg, 256, GEMM_SMEM>>>(gxr, gwr + 0 * DIM * DIM, gq, S_LEN, DIM, DIM);
    gemm_mma<<<gg, 256, GEMM_SMEM>>>(gxr, gwr + 1 * DIM * DIM, gk, S_LEN, DIM, DIM);
    gemm_mma<<<gg, 256, GEMM_SMEM>>>(gxr, gwr + 2 * DIM * DIM, gv, S_LEN, DIM, DIM);

    rope_table_kernel<<<(S_LEN * HALF_HD + 255) / 256, 256>>>();
    rope_apply_kernel<<<(S_LEN * NH * HALF_HD + 255) / 256, 256>>>(gq);
    rope_apply_kernel<<<(S_LEN * NH * HALF_HD + 255) / 256, 256>>>(gk);

    flash_attn_kernel<<<dim3(S_LEN / QT, NH), 128, FLASH_SMEM>>>();

    gemm_mma<<<gg, 256, GEMM_SMEM>>>(go, gwr + 3 * DIM * DIM, out, S_LEN, DIM, DIM);
}